// round 14
// baseline (speedup 1.0000x reference)
#include <cuda_runtime.h>
#include <cstdint>
#include <cstddef>

// Problem constants
#define BATCH   4
#define NHEAD   12
#define DH      64
#define HID     768
#define HDIM    32
#define WDIM    32
#define NTOK    1024
#define BH      48
#define MTOK    4096

// ---------------- scratch (device globals) ----------------
__device__ float g_q   [(size_t)BH * NTOK * DH];
__device__ float g_k   [(size_t)BH * NTOK * DH];
__device__ float g_kT  [(size_t)BH * DH * NTOK];
__device__ float g_v   [(size_t)BH * NTOK * DH];
__device__ float g_relh[(size_t)BH * NTOK * 32];
__device__ float g_relw[(size_t)BH * NTOK * 32];
__device__ float g_o   [(size_t)MTOK * HID];

// ---------------- f32x2 packed helpers ----------------
#define FMA2(d, a, b) \
    asm("fma.rn.f32x2 %0, %1, %2, %0;" : "+l"(d) : "l"(a), "l"(b))
#define MUL2(d, s) \
    asm("mul.rn.f32x2 %0, %0, %1;" : "+l"(d) : "l"(s))
#define PACK2(d, x, y) \
    asm("mov.b64 %0, {%1, %2};" : "=l"(d) : "r"(__float_as_uint(x)), "r"(__float_as_uint(y)))
#define UNPACK2(x, y, d) do {                                   \
    unsigned _lo, _hi;                                          \
    asm("mov.b64 {%0, %1}, %2;" : "=r"(_lo), "=r"(_hi) : "l"(d)); \
    x = __uint_as_float(_lo); y = __uint_as_float(_hi); } while (0)

// ================= 128x128x16 big core (8x8 micro) — qkv / out ===============
__device__ __forceinline__ void gemm_big_core(
    const float* __restrict__ A, int lda,
    const float* __restrict__ B, int ldb,
    int K, int m0, int n0, unsigned long long acc[4][8])
{
    __shared__ __align__(16) float As[16][132];
    __shared__ __align__(16) float Bs[16][132];

    const int tid = threadIdx.x;
    const int tx  = tid & 15;
    const int ty  = tid >> 4;

    const int ra  = tid >> 1;
    const int ka  = (tid & 1) << 3;
    const int krb = tid >> 4;
    const int qb  = (tid & 15) << 3;

    const float* pa = A + (size_t)(m0 + ra) * lda + ka;
    const float* pb = B + (size_t)krb * ldb + n0 + qb;

    float4 va0 = *reinterpret_cast<const float4*>(pa);
    float4 va1 = *reinterpret_cast<const float4*>(pa + 4);
    float4 vb0 = *reinterpret_cast<const float4*>(pb);
    float4 vb1 = *reinterpret_cast<const float4*>(pb + 4);

    #pragma unroll
    for (int ip = 0; ip < 4; ++ip)
        #pragma unroll
        for (int j = 0; j < 8; ++j) acc[ip][j] = 0ull;

    for (int k0 = 0; k0 < K; k0 += 16) {
        As[ka + 0][ra] = va0.x; As[ka + 1][ra] = va0.y;
        As[ka + 2][ra] = va0.z; As[ka + 3][ra] = va0.w;
        As[ka + 4][ra] = va1.x; As[ka + 5][ra] = va1.y;
        As[ka + 6][ra] = va1.z; As[ka + 7][ra] = va1.w;
        *reinterpret_cast<float4*>(&Bs[krb][qb])     = vb0;
        *reinterpret_cast<float4*>(&Bs[krb][qb + 4]) = vb1;
        __syncthreads();

        const int kn = k0 + 16;
        if (kn < K) {
            va0 = *reinterpret_cast<const float4*>(pa + kn);
            va1 = *reinterpret_cast<const float4*>(pa + kn + 4);
            vb0 = *reinterpret_cast<const float4*>(pb + (size_t)kn * ldb);
            vb1 = *reinterpret_cast<const float4*>(pb + (size_t)kn * ldb + 4);
        }

        #pragma unroll
        for (int kk = 0; kk < 16; ++kk) {
            const ulonglong2* ap =
                reinterpret_cast<const ulonglong2*>(&As[kk][ty << 3]);
            ulonglong2 aa = ap[0];
            ulonglong2 ab = ap[1];
            unsigned long long apair[4] = {aa.x, aa.y, ab.x, ab.y};
            float4 b0 = *reinterpret_cast<const float4*>(&Bs[kk][tx << 3]);
            float4 b1 = *reinterpret_cast<const float4*>(&Bs[kk][(tx << 3) + 4]);
            float bv[8] = {b0.x, b0.y, b0.z, b0.w, b1.x, b1.y, b1.z, b1.w};
            #pragma unroll
            for (int j = 0; j < 8; ++j) {
                unsigned long long bp;
                PACK2(bp, bv[j], bv[j]);
                #pragma unroll
                for (int ip = 0; ip < 4; ++ip)
                    FMA2(acc[ip][j], apair[ip], bp);
            }
        }
        __syncthreads();
    }
}

__device__ __forceinline__ void unpack_big(
    const unsigned long long acc[4][8], float r[8][8])
{
    #pragma unroll
    for (int ip = 0; ip < 4; ++ip)
        #pragma unroll
        for (int j = 0; j < 8; ++j)
            UNPACK2(r[2 * ip][j], r[2 * ip + 1][j], acc[ip][j]);
}

__device__ __forceinline__ void unpack_acc(
    const unsigned long long acc[4][4], float r[8][4])
{
    #pragma unroll
    for (int ip = 0; ip < 4; ++ip)
        #pragma unroll
        for (int j = 0; j < 4; ++j)
            UNPACK2(r[2 * ip][j], r[2 * ip + 1][j], acc[ip][j]);
}

// ---------------- 1) qkv = x @ w_qkv, scatter to g_q/g_k/g_v ----------------
__global__ __launch_bounds__(256) void k_gemm_qkv(
    const float* __restrict__ x, const float* __restrict__ w)
{
    const int m0 = blockIdx.y * 128;
    const int n0 = blockIdx.x * 128;
    unsigned long long acc[4][8];
    gemm_big_core(x, HID, w, 3 * NHEAD * DH, HID, m0, n0, acc);
    float r[8][8];
    unpack_big(acc, r);

    const int tx = threadIdx.x & 15;
    const int ty = threadIdx.x >> 4;
    const int nb   = n0 + (tx << 3);
    const int sel  = nb / (NHEAD * DH);
    const int head = (nb % (NHEAD * DH)) >> 6;
    const int cih  = nb & 63;
    float* dst = (sel == 0) ? g_q : (sel == 1) ? g_k : g_v;

    #pragma unroll
    for (int rr = 0; rr < 8; ++rr) {
        const int m = m0 + (ty << 3) + rr;
        const int b = m >> 10;
        const int tok = m & 1023;
        float* row = dst + (((size_t)(b * NHEAD + head) * NTOK + tok) << 6) + cih;
        *reinterpret_cast<float4*>(row) =
            make_float4(r[rr][0], r[rr][1], r[rr][2], r[rr][3]);
        *reinterpret_cast<float4*>(row + 4) =
            make_float4(r[rr][4], r[rr][5], r[rr][6], r[rr][7]);
    }
}

// ---------------- 2) transpose K ----------------
__global__ __launch_bounds__(256) void k_transpose()
{
    __shared__ float t[32][33];
    const int bh   = blockIdx.z;
    const int tok0 = blockIdx.x * 32;
    const int d0   = blockIdx.y * 32;
    const int x  = threadIdx.x;
    const int y0 = threadIdx.y;
    const float* src = g_k  + ((size_t)bh << 16);
    float*       dst = g_kT + ((size_t)bh << 16);
    #pragma unroll
    for (int yy = 0; yy < 32; yy += 8)
        t[y0 + yy][x] = src[(size_t)(tok0 + y0 + yy) * DH + d0 + x];
    __syncthreads();
    #pragma unroll
    for (int yy = 0; yy < 32; yy += 8)
        dst[(size_t)(d0 + y0 + yy) * NTOK + tok0 + x] = t[x][y0 + yy];
}

// ---------------- 3) rel_h / rel_w tables ----------------
__global__ __launch_bounds__(64) void k_rel(
    const float* __restrict__ rel_pos_h, const float* __restrict__ rel_pos_w)
{
    const int bh  = blockIdx.y;
    const int tok = blockIdx.x;
    __shared__ float qs[64];
    const int t = threadIdx.x;
    qs[t] = g_q[(((size_t)bh << 10) + tok) * DH + t];
    __syncthreads();

    const int qh = tok >> 5;
    const int qw = tok & 31;
    const float* rp;
    float* out;
    int ridx;
    if (t < 32) {
        rp = rel_pos_h; ridx = qh - t + (HDIM - 1);
        out = &g_relh[(((size_t)bh << 10) + tok) * 32 + t];
    } else {
        const int kw = t - 32;
        rp = rel_pos_w; ridx = qw - kw + (WDIM - 1);
        out = &g_relw[(((size_t)bh << 10) + tok) * 32 + kw];
    }
    const float* rr = rp + (size_t)ridx * DH;
    float s = 0.f;
    #pragma unroll
    for (int c = 0; c < 64; ++c) s = fmaf(qs[c], rr[c], s);
    *out = s;
}

// ---------------- 4) flash attention: softmax(QK^T*s + bias) @ V -> g_o -------
__global__ __launch_bounds__(256) void k_flash()
{
    __shared__ __align__(16) float As[16][132];
    __shared__ __align__(16) float Bs[16][68];
    __shared__ __align__(16) float Ps[64][132];

    const int bh = blockIdx.y;
    const int m0 = blockIdx.x * 128;
    const int tid = threadIdx.x;
    const int tx = tid & 15;
    const int ty = tid >> 4;

    const int ra  = tid >> 1;           // 0..127
    const int ka  = (tid & 1) << 3;     // 0/8
    const int krb = tid >> 4;           // 0..15
    const int qb  = (tid & 15) << 2;    // 0..60

    const float* Qb  = g_q  + ((size_t)bh << 16);   // (1024, 64)
    const float* KTb = g_kT + ((size_t)bh << 16);   // (64, 1024)
    const float* Vb  = g_v  + ((size_t)bh << 16);   // (1024, 64)

    unsigned long long oacc[4][4];
    #pragma unroll
    for (int ip = 0; ip < 4; ++ip)
        #pragma unroll
        for (int j = 0; j < 4; ++j) oacc[ip][j] = 0ull;
    float mrow[8], lrow[8];
    #pragma unroll
    for (int i = 0; i < 8; ++i) { mrow[i] = -3.4e38f; lrow[i] = 0.f; }

    const float* paq = Qb + (size_t)(m0 + ra) * DH + ka;   // Q chunk base

    for (int t = 0; t < 16; ++t) {
        // ===== S = Q @ KT[:, t*64..) : contraction over dh=64 =====
        unsigned long long sacc[4][4];
        #pragma unroll
        for (int ip = 0; ip < 4; ++ip)
            #pragma unroll
            for (int j = 0; j < 4; ++j) sacc[ip][j] = 0ull;
        {
            const float* pb = KTb + (size_t)krb * NTOK + t * 64 + qb;
            float4 va0 = *reinterpret_cast<const float4*>(paq);
            float4 va1 = *reinterpret_cast<const float4*>(paq + 4);
            float4 vb  = *reinterpret_cast<const float4*>(pb);

            for (int k0 = 0; k0 < 64; k0 += 16) {
                As[ka + 0][ra] = va0.x; As[ka + 1][ra] = va0.y;
                As[ka + 2][ra] = va0.z; As[ka + 3][ra] = va0.w;
                As[ka + 4][ra] = va1.x; As[ka + 5][ra] = va1.y;
                As[ka + 6][ra] = va1.z; As[ka + 7][ra] = va1.w;
                *reinterpret_cast<float4*>(&Bs[krb][qb]) = vb;
                __syncthreads();

                const int kn = k0 + 16;
                if (kn < 64) {
                    va0 = *reinterpret_cast<const float4*>(paq + kn);
                    va1 = *reinterpret_cast<const float4*>(paq + kn + 4);
                    vb  = *reinterpret_cast<const float4*>(pb + (size_t)kn * NTOK);
                }

                #pragma unroll
                for (int kk = 0; kk < 16; ++kk) {
                    const ulonglong2* ap =
                        reinterpret_cast<const ulonglong2*>(&As[kk][ty << 3]);
                    ulonglong2 aa = ap[0];
                    ulonglong2 ab = ap[1];
                    unsigned long long apair[4] = {aa.x, aa.y, ab.x, ab.y};
                    float4 b4 = *reinterpret_cast<const float4*>(&Bs[kk][tx << 2]);
                    unsigned long long bp[4];
                    PACK2(bp[0], b4.x, b4.x);
                    PACK2(bp[1], b4.y, b4.y);
                    PACK2(bp[2], b4.z, b4.z);
                    PACK2(bp[3], b4.w, b4.w);
                    #pragma unroll
                    for (int ip = 0; ip < 4; ++ip)
                        #pragma unroll
                        for (int j = 0; j < 4; ++j)
                            FMA2(sacc[ip][j], apair[ip], bp[j]);
                }
                __syncthreads();
            }
        }
        float r[8][4];
        unpack_acc(sacc, r);

        // ===== bias + online softmax (rows owned by ty; 16 tx lanes/row) =====
        const int col0 = t * 64 + (tx << 2);
        const int kh   = col0 >> 5;
        const int kw0  = col0 & 31;
        float scale_r[8];
        #pragma unroll
        for (int rr = 0; rr < 8; ++rr) {
            const int tok = m0 + (ty << 3) + rr;
            const float bias = g_relh[(((size_t)bh << 10) + tok) * 32 + kh];
            const float* rw = g_relw + (((size_t)bh << 10) + tok) * 32 + kw0;
            r[rr][0] = fmaf(r[rr][0], 0.125f, bias + rw[0]);
            r[rr][1] = fmaf(r[rr][1], 0.125f, bias + rw[1]);
            r[rr][2] = fmaf(r[rr][2], 0.125f, bias + rw[2]);
            r[rr][3] = fmaf(r[rr][3], 0.125f, bias + rw[3]);

            float mx = fmaxf(fmaxf(r[rr][0], r[rr][1]),
                             fmaxf(r[rr][2], r[rr][3]));
            #pragma unroll
            for (int o = 8; o > 0; o >>= 1)
                mx = fmaxf(mx, __shfl_xor_sync(0xffffffffu, mx, o));
            const float mnew = fmaxf(mrow[rr], mx);
            scale_r[rr] = __expf(mrow[rr] - mnew);
            mrow[rr] = mnew;

            float p0 = __expf(r[rr][0] - mnew);
            float p1 = __expf(r[rr][1] - mnew);
            float p2 = __expf(r[rr][2] - mnew);
            float p3 = __expf(r[rr][3] - mnew);
            float s = p0 + p1 + p2 + p3;
            #pragma unroll
            for (int o = 8; o > 0; o >>= 1)
                s += __shfl_xor_sync(0xffffffffu, s, o);
            lrow[rr] = lrow[rr] * scale_r[rr] + s;

            const int prow = (ty << 3) + rr;
            Ps[(tx << 2) + 0][prow] = p0;
            Ps[(tx << 2) + 1][prow] = p1;
            Ps[(tx << 2) + 2][prow] = p2;
            Ps[(tx << 2) + 3][prow] = p3;
        }
        // rescale O accumulator (packed row pairs)
        #pragma unroll
        for (int ip = 0; ip < 4; ++ip) {
            unsigned long long sc;
            PACK2(sc, scale_r[2 * ip], scale_r[2 * ip + 1]);
            #pragma unroll
            for (int j = 0; j < 4; ++j)
                MUL2(oacc[ip][j], sc);
        }
        __syncthreads();   // Ps visible to all

        // ===== O += P @ V[t*64.., :] : contraction over 64 kv toks =====
        {
            const float* pb = Vb + (size_t)(t * 64 + krb) * DH + qb;
            float4 vb = *reinterpret_cast<const float4*>(pb);
            for (int k0 = 0; k0 < 64; k0 += 16) {
                *reinterpret_cast<float4*>(&Bs[krb][qb]) = vb;
                __syncthreads();

                const int kn = k0 + 16;
                if (kn < 64)
                    vb = *reinterpret_cast<const float4*>(pb + (size_t)kn * DH);

                #pragma unroll
                for (int kk = 0; kk < 16; ++kk) {
                    const ulonglong2* ap =
                        reinterpret_cast<const ulonglong2*>(&Ps[k0 + kk][ty << 3]);
                    ulonglong2 aa = ap[0];
                    ulonglong2 ab = ap[1];
                    unsigned long long apair[4] = {aa.x, aa.y, ab.x, ab.y};
                    float4 b4 = *reinterpret_cast<const float4*>(&Bs[kk][tx << 2]);
                    unsigned long long bp[4];
                    PACK2(bp[0], b4.x, b4.x);
                    PACK2(bp[1], b4.y, b4.y);
                    PACK2(bp[2], b4.z, b4.z);
                    PACK2(bp[3], b4.w, b4.w);
                    #pragma unroll
                    for (int ip = 0; ip < 4; ++ip)
                        #pragma unroll
                        for (int j = 0; j < 4; ++j)
                            FMA2(oacc[ip][j], apair[ip], bp[j]);
                }
                __syncthreads();
            }
        }
    }

    // ===== epilogue: O / l -> g_o =====
    float r[8][4];
    unpack_acc(oacc, r);
    const int head = bh % NHEAD;
    const int b    = bh / NHEAD;
    #pragma unroll
    for (int rr = 0; rr < 8; ++rr) {
        const int tok = m0 + (ty << 3) + rr;
        const float inv = 1.0f / lrow[rr];
        float4 v4 = make_float4(r[rr][0] * inv, r[rr][1] * inv,
                                r[rr][2] * inv, r[rr][3] * inv);
        *reinterpret_cast<float4*>(
            &g_o[(size_t)(b * NTOK + tok) * HID + head * DH + (tx << 2)]) = v4;
    }
}

// ---------------- 5) final projection (big core) ----------------
__global__ __launch_bounds__(256) void k_out(
    const float* __restrict__ w, const float* __restrict__ bias,
    float* __restrict__ out)
{
    const int m0 = blockIdx.y * 128;
    const int n0 = blockIdx.x * 128;
    unsigned long long acc[4][8];
    gemm_big_core(g_o, HID, w, HID, HID, m0, n0, acc);
    float r[8][8];
    unpack_big(acc, r);

    const int tx = threadIdx.x & 15;
    const int ty = threadIdx.x >> 4;
    const int col0 = n0 + (tx << 3);
    float4 bb0 = *reinterpret_cast<const float4*>(&bias[col0]);
    float4 bb1 = *reinterpret_cast<const float4*>(&bias[col0 + 4]);

    #pragma unroll
    for (int rr = 0; rr < 8; ++rr) {
        const int m = m0 + (ty << 3) + rr;
        float* dst = &out[(size_t)m * HID + col0];
        *reinterpret_cast<float4*>(dst) =
            make_float4(r[rr][0] + bb0.x, r[rr][1] + bb0.y,
                        r[rr][2] + bb0.z, r[rr][3] + bb0.w);
        *reinterpret_cast<float4*>(dst + 4) =
            make_float4(r[rr][4] + bb1.x, r[rr][5] + bb1.y,
                        r[rr][6] + bb1.z, r[rr][7] + bb1.w);
    }
}

// ---------------- launcher ----------------
extern "C" void kernel_launch(void* const* d_in, const int* in_sizes, int n_in,
                              void* d_out, int out_size)
{
    const float* x         = (const float*)d_in[0];
    const float* w_qkv     = (const float*)d_in[1];
    const float* w_out     = (const float*)d_in[2];
    const float* b_out     = (const float*)d_in[3];
    const float* rel_pos_h = (const float*)d_in[4];
    const float* rel_pos_w = (const float*)d_in[5];
    float* out = (float*)d_out;

    k_gemm_qkv<<<dim3(18, 32), 256>>>(x, w_qkv);
    k_transpose<<<dim3(32, 2, BH), dim3(32, 8)>>>();
    k_rel<<<dim3(NTOK, BH), 64>>>(rel_pos_h, rel_pos_w);
    k_flash<<<dim3(8, BH), 256>>>();
    k_out<<<dim3(6, 32), 256>>>(w_out, b_out, out);
}

// round 15
// speedup vs baseline: 1.0211x; 1.0211x over previous
#include <cuda_runtime.h>
#include <cstdint>
#include <cstddef>

// Problem constants
#define BATCH   4
#define NHEAD   12
#define DH      64
#define HID     768
#define HDIM    32
#define WDIM    32
#define NTOK    1024
#define BH      48
#define MTOK    4096

// ---------------- scratch (device globals) ----------------
__device__ float g_q   [(size_t)BH * NTOK * DH];
__device__ float g_k   [(size_t)BH * NTOK * DH];
__device__ float g_kT  [(size_t)BH * DH * NTOK];
__device__ float g_v   [(size_t)BH * NTOK * DH];
__device__ float g_relh[(size_t)BH * NTOK * 32];
__device__ float g_relw[(size_t)BH * NTOK * 32];
__device__ float g_attn[(size_t)BH * NTOK * NTOK];
__device__ float g_o   [(size_t)MTOK * HID];

// ---------------- f32x2 packed helpers ----------------
#define FMA2(d, a, b) \
    asm("fma.rn.f32x2 %0, %1, %2, %0;" : "+l"(d) : "l"(a), "l"(b))
#define PACK2(d, x, y) \
    asm("mov.b64 %0, {%1, %2};" : "=l"(d) : "r"(__float_as_uint(x)), "r"(__float_as_uint(y)))
#define UNPACK2(x, y, d) do {                                   \
    unsigned _lo, _hi;                                          \
    asm("mov.b64 {%0, %1}, %2;" : "=r"(_lo), "=r"(_hi) : "l"(d)); \
    x = __uint_as_float(_lo); y = __uint_as_float(_hi); } while (0)

// ================= 128x128x16 big core (8x8 micro), double-buffered ==========
__device__ __forceinline__ void gemm_big_core(
    const float* __restrict__ A, int lda,
    const float* __restrict__ B, int ldb,
    int K, int m0, int n0, unsigned long long acc[4][8])
{
    __shared__ __align__(16) float As[2][16][132];
    __shared__ __align__(16) float Bs[2][16][132];

    const int tid = threadIdx.x;
    const int tx  = tid & 15;
    const int ty  = tid >> 4;

    const int ra  = tid >> 1;
    const int ka  = (tid & 1) << 3;
    const int krb = tid >> 4;
    const int qb  = (tid & 15) << 3;

    const float* pa = A + (size_t)(m0 + ra) * lda + ka;
    const float* pb = B + (size_t)krb * ldb + n0 + qb;

    float4 va0, va1, vb0, vb1;

    #pragma unroll
    for (int ip = 0; ip < 4; ++ip)
        #pragma unroll
        for (int j = 0; j < 8; ++j) acc[ip][j] = 0ull;

    const int nch = K >> 4;

    // stage chunk 0 into buf 0
    va0 = *reinterpret_cast<const float4*>(pa);
    va1 = *reinterpret_cast<const float4*>(pa + 4);
    vb0 = *reinterpret_cast<const float4*>(pb);
    vb1 = *reinterpret_cast<const float4*>(pb + 4);
    As[0][ka + 0][ra] = va0.x; As[0][ka + 1][ra] = va0.y;
    As[0][ka + 2][ra] = va0.z; As[0][ka + 3][ra] = va0.w;
    As[0][ka + 4][ra] = va1.x; As[0][ka + 5][ra] = va1.y;
    As[0][ka + 6][ra] = va1.z; As[0][ka + 7][ra] = va1.w;
    *reinterpret_cast<float4*>(&Bs[0][krb][qb])     = vb0;
    *reinterpret_cast<float4*>(&Bs[0][krb][qb + 4]) = vb1;
    if (nch > 1) {
        va0 = *reinterpret_cast<const float4*>(pa + 16);
        va1 = *reinterpret_cast<const float4*>(pa + 20);
        vb0 = *reinterpret_cast<const float4*>(pb + (size_t)16 * ldb);
        vb1 = *reinterpret_cast<const float4*>(pb + (size_t)16 * ldb + 4);
    }
    __syncthreads();

    for (int cc = 0; cc < nch; ++cc) {
        const int cur = cc & 1;
        if (cc + 1 < nch) {
            const int nxt = cur ^ 1;
            As[nxt][ka + 0][ra] = va0.x; As[nxt][ka + 1][ra] = va0.y;
            As[nxt][ka + 2][ra] = va0.z; As[nxt][ka + 3][ra] = va0.w;
            As[nxt][ka + 4][ra] = va1.x; As[nxt][ka + 5][ra] = va1.y;
            As[nxt][ka + 6][ra] = va1.z; As[nxt][ka + 7][ra] = va1.w;
            *reinterpret_cast<float4*>(&Bs[nxt][krb][qb])     = vb0;
            *reinterpret_cast<float4*>(&Bs[nxt][krb][qb + 4]) = vb1;
            if (cc + 2 < nch) {
                const int ko = (cc + 2) << 4;
                va0 = *reinterpret_cast<const float4*>(pa + ko);
                va1 = *reinterpret_cast<const float4*>(pa + ko + 4);
                vb0 = *reinterpret_cast<const float4*>(pb + (size_t)ko * ldb);
                vb1 = *reinterpret_cast<const float4*>(pb + (size_t)ko * ldb + 4);
            }
        }

        #pragma unroll
        for (int kk = 0; kk < 16; ++kk) {
            const ulonglong2* ap =
                reinterpret_cast<const ulonglong2*>(&As[cur][kk][ty << 3]);
            ulonglong2 aa = ap[0];
            ulonglong2 ab = ap[1];
            unsigned long long apair[4] = {aa.x, aa.y, ab.x, ab.y};
            float4 b0 = *reinterpret_cast<const float4*>(&Bs[cur][kk][tx << 3]);
            float4 b1 = *reinterpret_cast<const float4*>(&Bs[cur][kk][(tx << 3) + 4]);
            float bv[8] = {b0.x, b0.y, b0.z, b0.w, b1.x, b1.y, b1.z, b1.w};
            #pragma unroll
            for (int j = 0; j < 8; ++j) {
                unsigned long long bp;
                PACK2(bp, bv[j], bv[j]);
                #pragma unroll
                for (int ip = 0; ip < 4; ++ip)
                    FMA2(acc[ip][j], apair[ip], bp);
            }
        }
        __syncthreads();
    }
}

__device__ __forceinline__ void unpack_big(
    const unsigned long long acc[4][8], float r[8][8])
{
    #pragma unroll
    for (int ip = 0; ip < 4; ++ip)
        #pragma unroll
        for (int j = 0; j < 8; ++j)
            UNPACK2(r[2 * ip][j], r[2 * ip + 1][j], acc[ip][j]);
}

// ================= 128x64x16 core (8x4 micro), double-buffered ================
// EXP != 0: apply exp(a - sM[row]) at A smem-store (fused softmax for PV).
template<int EXP>
__device__ __forceinline__ void gemm_s_core(
    const float* __restrict__ A, int lda,
    const float* __restrict__ B, int ldb,
    int K, int m0, int n0, const float* __restrict__ sM,
    unsigned long long acc[4][4])
{
    __shared__ __align__(16) float As[2][16][132];
    __shared__ __align__(16) float Bs[2][16][68];

    const int tid = threadIdx.x;
    const int tx  = tid & 15;
    const int ty  = tid >> 4;

    const int ra  = tid >> 1;
    const int ka  = (tid & 1) << 3;
    const int krb = tid >> 4;
    const int qb  = (tid & 15) << 2;

    const float* pa = A + (size_t)(m0 + ra) * lda + ka;
    const float* pb = B + (size_t)krb * ldb + n0 + qb;
    const float Mr = EXP ? sM[ra] : 0.f;

    float4 va0, va1, vb;
    const int nch = K >> 4;

    #pragma unroll
    for (int ip = 0; ip < 4; ++ip)
        #pragma unroll
        for (int j = 0; j < 4; ++j) acc[ip][j] = 0ull;

    auto stA = [&](int buf, float4 a0, float4 a1) {
        if (EXP) {
            As[buf][ka + 0][ra] = __expf(a0.x - Mr);
            As[buf][ka + 1][ra] = __expf(a0.y - Mr);
            As[buf][ka + 2][ra] = __expf(a0.z - Mr);
            As[buf][ka + 3][ra] = __expf(a0.w - Mr);
            As[buf][ka + 4][ra] = __expf(a1.x - Mr);
            As[buf][ka + 5][ra] = __expf(a1.y - Mr);
            As[buf][ka + 6][ra] = __expf(a1.z - Mr);
            As[buf][ka + 7][ra] = __expf(a1.w - Mr);
        } else {
            As[buf][ka + 0][ra] = a0.x; As[buf][ka + 1][ra] = a0.y;
            As[buf][ka + 2][ra] = a0.z; As[buf][ka + 3][ra] = a0.w;
            As[buf][ka + 4][ra] = a1.x; As[buf][ka + 5][ra] = a1.y;
            As[buf][ka + 6][ra] = a1.z; As[buf][ka + 7][ra] = a1.w;
        }
    };

    va0 = *reinterpret_cast<const float4*>(pa);
    va1 = *reinterpret_cast<const float4*>(pa + 4);
    vb  = *reinterpret_cast<const float4*>(pb);
    stA(0, va0, va1);
    *reinterpret_cast<float4*>(&Bs[0][krb][qb]) = vb;
    if (nch > 1) {
        va0 = *reinterpret_cast<const float4*>(pa + 16);
        va1 = *reinterpret_cast<const float4*>(pa + 20);
        vb  = *reinterpret_cast<const float4*>(pb + (size_t)16 * ldb);
    }
    __syncthreads();

    for (int cc = 0; cc < nch; ++cc) {
        const int cur = cc & 1;
        if (cc + 1 < nch) {
            const int nxt = cur ^ 1;
            stA(nxt, va0, va1);
            *reinterpret_cast<float4*>(&Bs[nxt][krb][qb]) = vb;
            if (cc + 2 < nch) {
                const int ko = (cc + 2) << 4;
                va0 = *reinterpret_cast<const float4*>(pa + ko);
                va1 = *reinterpret_cast<const float4*>(pa + ko + 4);
                vb  = *reinterpret_cast<const float4*>(pb + (size_t)ko * ldb);
            }
        }

        #pragma unroll
        for (int kk = 0; kk < 16; ++kk) {
            const ulonglong2* ap =
                reinterpret_cast<const ulonglong2*>(&As[cur][kk][ty << 3]);
            ulonglong2 aa = ap[0];
            ulonglong2 ab = ap[1];
            unsigned long long apair[4] = {aa.x, aa.y, ab.x, ab.y};
            float4 b4 = *reinterpret_cast<const float4*>(&Bs[cur][kk][tx << 2]);
            unsigned long long bp[4];
            PACK2(bp[0], b4.x, b4.x);
            PACK2(bp[1], b4.y, b4.y);
            PACK2(bp[2], b4.z, b4.z);
            PACK2(bp[3], b4.w, b4.w);
            #pragma unroll
            for (int ip = 0; ip < 4; ++ip)
                #pragma unroll
                for (int j = 0; j < 4; ++j)
                    FMA2(acc[ip][j], apair[ip], bp[j]);
        }
        __syncthreads();
    }
}

__device__ __forceinline__ void unpack_acc(
    const unsigned long long acc[4][4], float r[8][4])
{
    #pragma unroll
    for (int ip = 0; ip < 4; ++ip)
        #pragma unroll
        for (int j = 0; j < 4; ++j)
            UNPACK2(r[2 * ip][j], r[2 * ip + 1][j], acc[ip][j]);
}

// ---------------- 1) qkv = x @ w_qkv, scatter to g_q/g_k/g_v ----------------
__global__ __launch_bounds__(256) void k_gemm_qkv(
    const float* __restrict__ x, const float* __restrict__ w)
{
    const int m0 = blockIdx.y * 128;
    const int n0 = blockIdx.x * 128;
    unsigned long long acc[4][8];
    gemm_big_core(x, HID, w, 3 * NHEAD * DH, HID, m0, n0, acc);
    float r[8][8];
    unpack_big(acc, r);

    const int tx = threadIdx.x & 15;
    const int ty = threadIdx.x >> 4;
    const int nb   = n0 + (tx << 3);
    const int sel  = nb / (NHEAD * DH);
    const int head = (nb % (NHEAD * DH)) >> 6;
    const int cih  = nb & 63;
    float* dst = (sel == 0) ? g_q : (sel == 1) ? g_k : g_v;

    #pragma unroll
    for (int rr = 0; rr < 8; ++rr) {
        const int m = m0 + (ty << 3) + rr;
        const int b = m >> 10;
        const int tok = m & 1023;
        float* row = dst + (((size_t)(b * NHEAD + head) * NTOK + tok) << 6) + cih;
        *reinterpret_cast<float4*>(row) =
            make_float4(r[rr][0], r[rr][1], r[rr][2], r[rr][3]);
        *reinterpret_cast<float4*>(row + 4) =
            make_float4(r[rr][4], r[rr][5], r[rr][6], r[rr][7]);
    }
}

// ---------------- 2) transpose K ----------------
__global__ __launch_bounds__(256) void k_transpose()
{
    __shared__ float t[32][33];
    const int bh   = blockIdx.z;
    const int tok0 = blockIdx.x * 32;
    const int d0   = blockIdx.y * 32;
    const int x  = threadIdx.x;
    const int y0 = threadIdx.y;
    const float* src = g_k  + ((size_t)bh << 16);
    float*       dst = g_kT + ((size_t)bh << 16);
    #pragma unroll
    for (int yy = 0; yy < 32; yy += 8)
        t[y0 + yy][x] = src[(size_t)(tok0 + y0 + yy) * DH + d0 + x];
    __syncthreads();
    #pragma unroll
    for (int yy = 0; yy < 32; yy += 8)
        dst[(size_t)(d0 + y0 + yy) * NTOK + tok0 + x] = t[x][y0 + yy];
}

// ---------------- 3) rel_h / rel_w tables ----------------
__global__ __launch_bounds__(64) void k_rel(
    const float* __restrict__ rel_pos_h, const float* __restrict__ rel_pos_w)
{
    const int bh  = blockIdx.y;
    const int tok = blockIdx.x;
    __shared__ float qs[64];
    const int t = threadIdx.x;
    qs[t] = g_q[(((size_t)bh << 10) + tok) * DH + t];
    __syncthreads();

    const int qh = tok >> 5;
    const int qw = tok & 31;
    const float* rp;
    float* out;
    int ridx;
    if (t < 32) {
        rp = rel_pos_h; ridx = qh - t + (HDIM - 1);
        out = &g_relh[(((size_t)bh << 10) + tok) * 32 + t];
    } else {
        const int kw = t - 32;
        rp = rel_pos_w; ridx = qw - kw + (WDIM - 1);
        out = &g_relw[(((size_t)bh << 10) + tok) * 32 + kw];
    }
    const float* rr = rp + (size_t)ridx * DH;
    float s = 0.f;
    #pragma unroll
    for (int c = 0; c < 64; ++c) s = fmaf(qs[c], rr[c], s);
    *out = s;
}

// ---------------- 4) logits = scale*Q@K^T + rel_h + rel_w ----------------
__global__ __launch_bounds__(256) void k_logits()
{
    const int bh = blockIdx.z;
    const int m0 = blockIdx.y * 128;
    const int n0 = blockIdx.x * 64;
    const float* A = g_q  + ((size_t)bh << 16);
    const float* B = g_kT + ((size_t)bh << 16);
    unsigned long long acc[4][4];
    gemm_s_core<0>(A, DH, B, NTOK, DH, m0, n0, nullptr, acc);
    float r[8][4];
    unpack_acc(acc, r);

    const int tx = threadIdx.x & 15;
    const int ty = threadIdx.x >> 4;
    const float scale = 0.125f;
    const int col0 = n0 + (tx << 2);
    const int kh   = col0 >> 5;
    const int kw0  = col0 & 31;
    float* outb = g_attn + ((size_t)bh << 20);

    #pragma unroll
    for (int rr = 0; rr < 8; ++rr) {
        const int tok = m0 + (ty << 3) + rr;
        const float* rh = g_relh + (((size_t)bh << 10) + tok) * 32;
        const float* rw = g_relw + (((size_t)bh << 10) + tok) * 32;
        const float bias = rh[kh];
        float4 v;
        v.x = fmaf(r[rr][0], scale, bias + rw[kw0 + 0]);
        v.y = fmaf(r[rr][1], scale, bias + rw[kw0 + 1]);
        v.z = fmaf(r[rr][2], scale, bias + rw[kw0 + 2]);
        v.w = fmaf(r[rr][3], scale, bias + rw[kw0 + 3]);
        *reinterpret_cast<float4*>(&outb[((size_t)tok << 10) + col0]) = v;
    }
}

// ---------------- 5) fused softmax + PV ----------------
__global__ __launch_bounds__(256) void k_pv()
{
    __shared__ float sM[128];
    __shared__ float sInvL[128];

    const int bh = blockIdx.y;
    const int m0 = blockIdx.x * 128;
    const int tid = threadIdx.x;
    const int warp = tid >> 5, lane = tid & 31;

    // prepass: per row, load all 8 float4 (MLP=8), then max, then sum of exps
    const float* attnb = g_attn + ((size_t)bh << 20);
    for (int rr = 0; rr < 16; ++rr) {
        const int rloc = warp * 16 + rr;
        const float4* p = (const float4*)(attnb + ((size_t)(m0 + rloc) << 10));
        float4 v[8];
        #pragma unroll
        for (int i = 0; i < 8; ++i) v[i] = p[lane + i * 32];

        float m = -3.4e38f;
        #pragma unroll
        for (int i = 0; i < 8; ++i)
            m = fmaxf(m, fmaxf(fmaxf(v[i].x, v[i].y), fmaxf(v[i].z, v[i].w)));
        #pragma unroll
        for (int o = 16; o > 0; o >>= 1)
            m = fmaxf(m, __shfl_xor_sync(0xffffffffu, m, o));

        float l = 0.f;
        #pragma unroll
        for (int i = 0; i < 8; ++i)
            l += __expf(v[i].x - m) + __expf(v[i].y - m)
               + __expf(v[i].z - m) + __expf(v[i].w - m);
        #pragma unroll
        for (int o = 16; o > 0; o >>= 1)
            l += __shfl_xor_sync(0xffffffffu, l, o);

        if (lane == 0) { sM[rloc] = m; sInvL[rloc] = 1.0f / l; }
    }
    __syncthreads();

    unsigned long long acc[4][4];
    gemm_s_core<1>(attnb, NTOK,
                   g_v + ((size_t)bh << 16), DH,
                   NTOK, m0, 0, sM, acc);
    float r[8][4];
    unpack_acc(acc, r);

    const int tx = tid & 15;
    const int ty = tid >> 4;
    const int head = bh % NHEAD;
    const int b    = bh / NHEAD;

    #pragma unroll
    for (int rr = 0; rr < 8; ++rr) {
        const int rloc = (ty << 3) + rr;
        const int tok = m0 + rloc;
        const float inv = sInvL[rloc];
        float4 v4 = make_float4(r[rr][0] * inv, r[rr][1] * inv,
                                r[rr][2] * inv, r[rr][3] * inv);
        *reinterpret_cast<float4*>(
            &g_o[(size_t)(b * NTOK + tok) * HID + head * DH + (tx << 2)]) = v4;
    }
}

// ---------------- 6) final projection (big core) ----------------
__global__ __launch_bounds__(256) void k_out(
    const float* __restrict__ w, const float* __restrict__ bias,
    float* __restrict__ out)
{
    const int m0 = blockIdx.y * 128;
    const int n0 = blockIdx.x * 128;
    unsigned long long acc[4][8];
    gemm_big_core(g_o, HID, w, HID, HID, m0, n0, acc);
    float r[8][8];
    unpack_big(acc, r);

    const int tx = threadIdx.x & 15;
    const int ty = threadIdx.x >> 4;
    const int col0 = n0 + (tx << 3);
    float4 bb0 = *reinterpret_cast<const float4*>(&bias[col0]);
    float4 bb1 = *reinterpret_cast<const float4*>(&bias[col0 + 4]);

    #pragma unroll
    for (int rr = 0; rr < 8; ++rr) {
        const int m = m0 + (ty << 3) + rr;
        float* dst = &out[(size_t)m * HID + col0];
        *reinterpret_cast<float4*>(dst) =
            make_float4(r[rr][0] + bb0.x, r[rr][1] + bb0.y,
                        r[rr][2] + bb0.z, r[rr][3] + bb0.w);
        *reinterpret_cast<float4*>(dst + 4) =
            make_float4(r[rr][4] + bb1.x, r[rr][5] + bb1.y,
                        r[rr][6] + bb1.z, r[rr][7] + bb1.w);
    }
}

// ---------------- launcher ----------------
extern "C" void kernel_launch(void* const* d_in, const int* in_sizes, int n_in,
                              void* d_out, int out_size)
{
    const float* x         = (const float*)d_in[0];
    const float* w_qkv     = (const float*)d_in[1];
    const float* w_out     = (const float*)d_in[2];
    const float* b_out     = (const float*)d_in[3];
    const float* rel_pos_h = (const float*)d_in[4];
    const float* rel_pos_w = (const float*)d_in[5];
    float* out = (float*)d_out;

    k_gemm_qkv<<<dim3(18, 32), 256>>>(x, w_qkv);
    k_transpose<<<dim3(32, 2, BH), dim3(32, 8)>>>();
    k_rel<<<dim3(NTOK, BH), 64>>>(rel_pos_h, rel_pos_w);
    k_logits<<<dim3(16, 8, BH), 256>>>();
    k_pv<<<dim3(8, BH), 256>>>();
    k_out<<<dim3(6, 32), 256>>>(w_out, b_out, out);
}

// round 16
// speedup vs baseline: 1.0321x; 1.0108x over previous
#include <cuda_runtime.h>
#include <cstdint>
#include <cstddef>

// Problem constants
#define BATCH   4
#define NHEAD   12
#define DH      64
#define HID     768
#define HDIM    32
#define WDIM    32
#define NTOK    1024
#define BH      48
#define MTOK    4096

// ---------------- scratch (device globals) ----------------
__device__ float g_q   [(size_t)BH * NTOK * DH];
__device__ float g_kT  [(size_t)BH * DH * NTOK];
__device__ float g_v   [(size_t)BH * NTOK * DH];
__device__ float g_relh[(size_t)BH * NTOK * 32];
__device__ float g_relw[(size_t)BH * NTOK * 32];
__device__ float g_attn[(size_t)BH * NTOK * NTOK];
__device__ float g_pm  [(size_t)BH * NTOK * 16];   // partial max  per (bh,tok,ntile)
__device__ float g_pl  [(size_t)BH * NTOK * 16];   // partial sumexp
__device__ float g_o   [(size_t)MTOK * HID];

// ---------------- f32x2 packed helpers ----------------
#define FMA2(d, a, b) \
    asm("fma.rn.f32x2 %0, %1, %2, %0;" : "+l"(d) : "l"(a), "l"(b))
#define PACK2(d, x, y) \
    asm("mov.b64 %0, {%1, %2};" : "=l"(d) : "r"(__float_as_uint(x)), "r"(__float_as_uint(y)))
#define UNPACK2(x, y, d) do {                                   \
    unsigned _lo, _hi;                                          \
    asm("mov.b64 {%0, %1}, %2;" : "=r"(_lo), "=r"(_hi) : "l"(d)); \
    x = __uint_as_float(_lo); y = __uint_as_float(_hi); } while (0)

// ================= 128x128x16 big core (8x8 micro) — qkv / out ===============
__device__ __forceinline__ void gemm_big_core(
    const float* __restrict__ A, int lda,
    const float* __restrict__ B, int ldb,
    int K, int m0, int n0, unsigned long long acc[4][8])
{
    __shared__ __align__(16) float As[16][132];
    __shared__ __align__(16) float Bs[16][132];

    const int tid = threadIdx.x;
    const int tx  = tid & 15;
    const int ty  = tid >> 4;

    const int ra  = tid >> 1;
    const int ka  = (tid & 1) << 3;
    const int krb = tid >> 4;
    const int qb  = (tid & 15) << 3;

    const float* pa = A + (size_t)(m0 + ra) * lda + ka;
    const float* pb = B + (size_t)krb * ldb + n0 + qb;

    float4 va0 = *reinterpret_cast<const float4*>(pa);
    float4 va1 = *reinterpret_cast<const float4*>(pa + 4);
    float4 vb0 = *reinterpret_cast<const float4*>(pb);
    float4 vb1 = *reinterpret_cast<const float4*>(pb + 4);

    #pragma unroll
    for (int ip = 0; ip < 4; ++ip)
        #pragma unroll
        for (int j = 0; j < 8; ++j) acc[ip][j] = 0ull;

    for (int k0 = 0; k0 < K; k0 += 16) {
        As[ka + 0][ra] = va0.x; As[ka + 1][ra] = va0.y;
        As[ka + 2][ra] = va0.z; As[ka + 3][ra] = va0.w;
        As[ka + 4][ra] = va1.x; As[ka + 5][ra] = va1.y;
        As[ka + 6][ra] = va1.z; As[ka + 7][ra] = va1.w;
        *reinterpret_cast<float4*>(&Bs[krb][qb])     = vb0;
        *reinterpret_cast<float4*>(&Bs[krb][qb + 4]) = vb1;
        __syncthreads();

        const int kn = k0 + 16;
        if (kn < K) {
            va0 = *reinterpret_cast<const float4*>(pa + kn);
            va1 = *reinterpret_cast<const float4*>(pa + kn + 4);
            vb0 = *reinterpret_cast<const float4*>(pb + (size_t)kn * ldb);
            vb1 = *reinterpret_cast<const float4*>(pb + (size_t)kn * ldb + 4);
        }

        #pragma unroll
        for (int kk = 0; kk < 16; ++kk) {
            const ulonglong2* ap =
                reinterpret_cast<const ulonglong2*>(&As[kk][ty << 3]);
            ulonglong2 aa = ap[0];
            ulonglong2 ab = ap[1];
            unsigned long long apair[4] = {aa.x, aa.y, ab.x, ab.y};
            float4 b0 = *reinterpret_cast<const float4*>(&Bs[kk][tx << 3]);
            float4 b1 = *reinterpret_cast<const float4*>(&Bs[kk][(tx << 3) + 4]);
            float bv[8] = {b0.x, b0.y, b0.z, b0.w, b1.x, b1.y, b1.z, b1.w};
            #pragma unroll
            for (int j = 0; j < 8; ++j) {
                unsigned long long bp;
                PACK2(bp, bv[j], bv[j]);
                #pragma unroll
                for (int ip = 0; ip < 4; ++ip)
                    FMA2(acc[ip][j], apair[ip], bp);
            }
        }
        __syncthreads();
    }
}

__device__ __forceinline__ void unpack_big(
    const unsigned long long acc[4][8], float r[8][8])
{
    #pragma unroll
    for (int ip = 0; ip < 4; ++ip)
        #pragma unroll
        for (int j = 0; j < 8; ++j)
            UNPACK2(r[2 * ip][j], r[2 * ip + 1][j], acc[ip][j]);
}

// ================= 128x64x16 core (8x4 micro), single-buffered ================
// EXP != 0: apply exp(a - sM[row]) at A smem-store (fused softmax for PV).
template<int EXP>
__device__ __forceinline__ void gemm_s_core(
    const float* __restrict__ A, int lda,
    const float* __restrict__ B, int ldb,
    int K, int m0, int n0, const float* __restrict__ sM,
    unsigned long long acc[4][4])
{
    __shared__ __align__(16) float As[16][132];
    __shared__ __align__(16) float Bs[16][68];

    const int tid = threadIdx.x;
    const int tx  = tid & 15;
    const int ty  = tid >> 4;

    const int ra  = tid >> 1;
    const int ka  = (tid & 1) << 3;
    const int krb = tid >> 4;
    const int qb  = (tid & 15) << 2;

    const float* pa = A + (size_t)(m0 + ra) * lda + ka;
    const float* pb = B + (size_t)krb * ldb + n0 + qb;
    const float Mr = EXP ? sM[ra] : 0.f;

    float4 va0 = *reinterpret_cast<const float4*>(pa);
    float4 va1 = *reinterpret_cast<const float4*>(pa + 4);
    float4 vb  = *reinterpret_cast<const float4*>(pb);

    #pragma unroll
    for (int ip = 0; ip < 4; ++ip)
        #pragma unroll
        for (int j = 0; j < 4; ++j) acc[ip][j] = 0ull;

    for (int k0 = 0; k0 < K; k0 += 16) {
        if (EXP) {
            As[ka + 0][ra] = __expf(va0.x - Mr);
            As[ka + 1][ra] = __expf(va0.y - Mr);
            As[ka + 2][ra] = __expf(va0.z - Mr);
            As[ka + 3][ra] = __expf(va0.w - Mr);
            As[ka + 4][ra] = __expf(va1.x - Mr);
            As[ka + 5][ra] = __expf(va1.y - Mr);
            As[ka + 6][ra] = __expf(va1.z - Mr);
            As[ka + 7][ra] = __expf(va1.w - Mr);
        } else {
            As[ka + 0][ra] = va0.x; As[ka + 1][ra] = va0.y;
            As[ka + 2][ra] = va0.z; As[ka + 3][ra] = va0.w;
            As[ka + 4][ra] = va1.x; As[ka + 5][ra] = va1.y;
            As[ka + 6][ra] = va1.z; As[ka + 7][ra] = va1.w;
        }
        *reinterpret_cast<float4*>(&Bs[krb][qb]) = vb;
        __syncthreads();

        const int kn = k0 + 16;
        if (kn < K) {
            va0 = *reinterpret_cast<const float4*>(pa + kn);
            va1 = *reinterpret_cast<const float4*>(pa + kn + 4);
            vb  = *reinterpret_cast<const float4*>(pb + (size_t)kn * ldb);
        }

        #pragma unroll
        for (int kk = 0; kk < 16; ++kk) {
            const ulonglong2* ap =
                reinterpret_cast<const ulonglong2*>(&As[kk][ty << 3]);
            ulonglong2 aa = ap[0];
            ulonglong2 ab = ap[1];
            unsigned long long apair[4] = {aa.x, aa.y, ab.x, ab.y};
            float4 b4 = *reinterpret_cast<const float4*>(&Bs[kk][tx << 2]);
            unsigned long long bp[4];
            PACK2(bp[0], b4.x, b4.x);
            PACK2(bp[1], b4.y, b4.y);
            PACK2(bp[2], b4.z, b4.z);
            PACK2(bp[3], b4.w, b4.w);
            #pragma unroll
            for (int ip = 0; ip < 4; ++ip)
                #pragma unroll
                for (int j = 0; j < 4; ++j)
                    FMA2(acc[ip][j], apair[ip], bp[j]);
        }
        __syncthreads();
    }
}

__device__ __forceinline__ void unpack_acc(
    const unsigned long long acc[4][4], float r[8][4])
{
    #pragma unroll
    for (int ip = 0; ip < 4; ++ip)
        #pragma unroll
        for (int j = 0; j < 4; ++j)
            UNPACK2(r[2 * ip][j], r[2 * ip + 1][j], acc[ip][j]);
}

// ---------------- 1) qkv = x @ w_qkv; scatter q, kT (transposed), v ------------
__global__ __launch_bounds__(256) void k_gemm_qkv(
    const float* __restrict__ x, const float* __restrict__ w)
{
    const int m0 = blockIdx.y * 128;
    const int n0 = blockIdx.x * 128;
    unsigned long long acc[4][8];
    gemm_big_core(x, HID, w, 3 * NHEAD * DH, HID, m0, n0, acc);
    float r[8][8];
    unpack_big(acc, r);

    const int tx = threadIdx.x & 15;
    const int ty = threadIdx.x >> 4;
    const int nb   = n0 + (tx << 3);
    const int sel  = nb / (NHEAD * DH);
    const int head = (nb % (NHEAD * DH)) >> 6;
    const int cih  = nb & 63;
    const int b    = m0 >> 10;               // constant per CTA
    const int tokb = (m0 & 1023) + (ty << 3);

    if (sel == 1) {
        // K: transposed scatter into g_kT[(bh, d, tok)]
        #pragma unroll
        for (int j = 0; j < 8; ++j) {
            float* col = g_kT
                + ((size_t)(b * NHEAD + head) * DH + cih + j) * NTOK + tokb;
            *reinterpret_cast<float4*>(col) =
                make_float4(r[0][j], r[1][j], r[2][j], r[3][j]);
            *reinterpret_cast<float4*>(col + 4) =
                make_float4(r[4][j], r[5][j], r[6][j], r[7][j]);
        }
    } else {
        float* dst = (sel == 0) ? g_q : g_v;
        #pragma unroll
        for (int rr = 0; rr < 8; ++rr) {
            const int tok = tokb + rr;
            float* row = dst
                + (((size_t)(b * NHEAD + head) * NTOK + tok) << 6) + cih;
            *reinterpret_cast<float4*>(row) =
                make_float4(r[rr][0], r[rr][1], r[rr][2], r[rr][3]);
            *reinterpret_cast<float4*>(row + 4) =
                make_float4(r[rr][4], r[rr][5], r[rr][6], r[rr][7]);
        }
    }
}

// ---------------- 2) rel_h / rel_w tables ----------------
__global__ __launch_bounds__(64) void k_rel(
    const float* __restrict__ rel_pos_h, const float* __restrict__ rel_pos_w)
{
    const int bh  = blockIdx.y;
    const int tok = blockIdx.x;
    __shared__ float qs[64];
    const int t = threadIdx.x;
    qs[t] = g_q[(((size_t)bh << 10) + tok) * DH + t];
    __syncthreads();

    const int qh = tok >> 5;
    const int qw = tok & 31;
    const float* rp;
    float* out;
    int ridx;
    if (t < 32) {
        rp = rel_pos_h; ridx = qh - t + (HDIM - 1);
        out = &g_relh[(((size_t)bh << 10) + tok) * 32 + t];
    } else {
        const int kw = t - 32;
        rp = rel_pos_w; ridx = qw - kw + (WDIM - 1);
        out = &g_relw[(((size_t)bh << 10) + tok) * 32 + kw];
    }
    const float* rr = rp + (size_t)ridx * DH;
    float s = 0.f;
    #pragma unroll
    for (int c = 0; c < 64; ++c) s = fmaf(qs[c], rr[c], s);
    *out = s;
}

// ---------------- 3) logits + bias + partial softmax stats ----------------
__global__ __launch_bounds__(256) void k_logits()
{
    const int bh = blockIdx.z;
    const int m0 = blockIdx.y * 128;
    const int n0 = blockIdx.x * 64;
    const float* A = g_q  + ((size_t)bh << 16);
    const float* B = g_kT + ((size_t)bh << 16);
    unsigned long long acc[4][4];
    gemm_s_core<0>(A, DH, B, NTOK, DH, m0, n0, nullptr, acc);
    float r[8][4];
    unpack_acc(acc, r);

    const int tx = threadIdx.x & 15;
    const int ty = threadIdx.x >> 4;
    const float scale = 0.125f;
    const int col0 = n0 + (tx << 2);
    const int kh   = col0 >> 5;
    const int kw0  = col0 & 31;
    const int ntile = blockIdx.x;          // 64-col tile index
    float* outb = g_attn + ((size_t)bh << 20);

    #pragma unroll
    for (int rr = 0; rr < 8; ++rr) {
        const int tok = m0 + (ty << 3) + rr;
        const float* rh = g_relh + (((size_t)bh << 10) + tok) * 32;
        const float* rw = g_relw + (((size_t)bh << 10) + tok) * 32;
        const float bias = rh[kh];
        float4 v;
        v.x = fmaf(r[rr][0], scale, bias + rw[kw0 + 0]);
        v.y = fmaf(r[rr][1], scale, bias + rw[kw0 + 1]);
        v.z = fmaf(r[rr][2], scale, bias + rw[kw0 + 2]);
        v.w = fmaf(r[rr][3], scale, bias + rw[kw0 + 3]);
        *reinterpret_cast<float4*>(&outb[((size_t)tok << 10) + col0]) = v;

        // partial (max, sumexp) over this row's 64-col segment (16 lanes)
        float mx = fmaxf(fmaxf(v.x, v.y), fmaxf(v.z, v.w));
        #pragma unroll
        for (int o = 8; o > 0; o >>= 1)
            mx = fmaxf(mx, __shfl_xor_sync(0xffffffffu, mx, o));
        float s = __expf(v.x - mx) + __expf(v.y - mx)
                + __expf(v.z - mx) + __expf(v.w - mx);
        #pragma unroll
        for (int o = 8; o > 0; o >>= 1)
            s += __shfl_xor_sync(0xffffffffu, s, o);
        if (tx == 0) {
            const size_t pidx = ((size_t)bh << 14) + ((size_t)tok << 4) + ntile;
            g_pm[pidx] = mx;
            g_pl[pidx] = s;
        }
    }
}

// ---------------- 4) fused softmax + PV ----------------
__global__ __launch_bounds__(256) void k_pv()
{
    __shared__ float sM[128];
    __shared__ float sInvL[128];

    const int bh = blockIdx.y;
    const int m0 = blockIdx.x * 128;
    const int tid = threadIdx.x;

    // combine 16 partial (m, l) per row
    if (tid < 128) {
        const int tok = m0 + tid;
        const float4* pm = (const float4*)(g_pm + ((size_t)bh << 14) + ((size_t)tok << 4));
        const float4* pl = (const float4*)(g_pl + ((size_t)bh << 14) + ((size_t)tok << 4));
        float4 m4[4] = {pm[0], pm[1], pm[2], pm[3]};
        float4 l4[4] = {pl[0], pl[1], pl[2], pl[3]};
        float M = -3.4e38f;
        #pragma unroll
        for (int i = 0; i < 4; ++i)
            M = fmaxf(M, fmaxf(fmaxf(m4[i].x, m4[i].y), fmaxf(m4[i].z, m4[i].w)));
        float L = 0.f;
        #pragma unroll
        for (int i = 0; i < 4; ++i) {
            L += l4[i].x * __expf(m4[i].x - M);
            L += l4[i].y * __expf(m4[i].y - M);
            L += l4[i].z * __expf(m4[i].z - M);
            L += l4[i].w * __expf(m4[i].w - M);
        }
        sM[tid] = M;
        sInvL[tid] = 1.0f / L;
    }
    __syncthreads();

    unsigned long long acc[4][4];
    gemm_s_core<1>(g_attn + ((size_t)bh << 20), NTOK,
                   g_v + ((size_t)bh << 16), DH,
                   NTOK, m0, 0, sM, acc);
    float r[8][4];
    unpack_acc(acc, r);

    const int tx = tid & 15;
    const int ty = tid >> 4;
    const int head = bh % NHEAD;
    const int b    = bh / NHEAD;

    #pragma unroll
    for (int rr = 0; rr < 8; ++rr) {
        const int rloc = (ty << 3) + rr;
        const int tok = m0 + rloc;
        const float inv = sInvL[rloc];
        float4 v4 = make_float4(r[rr][0] * inv, r[rr][1] * inv,
                                r[rr][2] * inv, r[rr][3] * inv);
        *reinterpret_cast<float4*>(
            &g_o[(size_t)(b * NTOK + tok) * HID + head * DH + (tx << 2)]) = v4;
    }
}

// ---------------- 5) final projection (big core) ----------------
__global__ __launch_bounds__(256) void k_out(
    const float* __restrict__ w, const float* __restrict__ bias,
    float* __restrict__ out)
{
    const int m0 = blockIdx.y * 128;
    const int n0 = blockIdx.x * 128;
    unsigned long long acc[4][8];
    gemm_big_core(g_o, HID, w, HID, HID, m0, n0, acc);
    float r[8][8];
    unpack_big(acc, r);

    const int tx = threadIdx.x & 15;
    const int ty = threadIdx.x >> 4;
    const int col0 = n0 + (tx << 3);
    float4 bb0 = *reinterpret_cast<const float4*>(&bias[col0]);
    float4 bb1 = *reinterpret_cast<const float4*>(&bias[col0 + 4]);

    #pragma unroll
    for (int rr = 0; rr < 8; ++rr) {
        const int m = m0 + (ty << 3) + rr;
        float* dst = &out[(size_t)m * HID + col0];
        *reinterpret_cast<float4*>(dst) =
            make_float4(r[rr][0] + bb0.x, r[rr][1] + bb0.y,
                        r[rr][2] + bb0.z, r[rr][3] + bb0.w);
        *reinterpret_cast<float4*>(dst + 4) =
            make_float4(r[rr][4] + bb1.x, r[rr][5] + bb1.y,
                        r[rr][6] + bb1.z, r[rr][7] + bb1.w);
    }
}

// ---------------- launcher ----------------
extern "C" void kernel_launch(void* const* d_in, const int* in_sizes, int n_in,
                              void* d_out, int out_size)
{
    const float* x         = (const float*)d_in[0];
    const float* w_qkv     = (const float*)d_in[1];
    const float* w_out     = (const float*)d_in[2];
    const float* b_out     = (const float*)d_in[3];
    const float* rel_pos_h = (const float*)d_in[4];
    const float* rel_pos_w = (const float*)d_in[5];
    float* out = (float*)d_out;

    k_gemm_qkv<<<dim3(18, 32), 256>>>(x, w_qkv);
    k_rel<<<dim3(NTOK, BH), 64>>>(rel_pos_h, rel_pos_w);
    k_logits<<<dim3(16, 8, BH), 256>>>();
    k_pv<<<dim3(8, BH), 256>>>();
    k_out<<<dim3(6, 32), 256>>>(w_out, b_out, out);
}

// round 17
// speedup vs baseline: 1.6663x; 1.6145x over previous
#include <cuda_runtime.h>
#include <cstdint>
#include <cstddef>

// Problem constants
#define BATCH   4
#define NHEAD   12
#define DH      64
#define HID     768
#define HDIM    32
#define WDIM    32
#define NTOK    1024
#define BH      48
#define MTOK    4096

// ---------------- scratch (device globals) ----------------
__device__ float g_q   [(size_t)BH * NTOK * DH];
__device__ float g_kT  [(size_t)BH * DH * NTOK];
__device__ float g_v   [(size_t)BH * NTOK * DH];
__device__ float g_relh[(size_t)BH * NTOK * 32];
__device__ float g_relw[(size_t)BH * NTOK * 32];
__device__ float g_attn[(size_t)BH * NTOK * NTOK];
__device__ float g_pm  [(size_t)BH * NTOK * 16];
__device__ float g_pl  [(size_t)BH * NTOK * 16];
__device__ float g_o   [(size_t)MTOK * HID];

// ---------------- f32x2 packed helpers ----------------
#define FMA2(d, a, b) \
    asm("fma.rn.f32x2 %0, %1, %2, %0;" : "+l"(d) : "l"(a), "l"(b))
#define PACK2(d, x, y) \
    asm("mov.b64 %0, {%1, %2};" : "=l"(d) : "r"(__float_as_uint(x)), "r"(__float_as_uint(y)))
#define UNPACK2(x, y, d) do {                                   \
    unsigned _lo, _hi;                                          \
    asm("mov.b64 {%0, %1}, %2;" : "=r"(_lo), "=r"(_hi) : "l"(d)); \
    x = __uint_as_float(_lo); y = __uint_as_float(_hi); } while (0)

// ================= 128x128x16 big core (8x8 micro) — qkv / out ===============
__device__ __forceinline__ void gemm_big_core(
    const float* __restrict__ A, int lda,
    const float* __restrict__ B, int ldb,
    int K, int m0, int n0, unsigned long long acc[4][8])
{
    __shared__ __align__(16) float As[16][132];
    __shared__ __align__(16) float Bs[16][132];

    const int tid = threadIdx.x;
    const int tx  = tid & 15;
    const int ty  = tid >> 4;

    const int ra  = tid >> 1;
    const int ka  = (tid & 1) << 3;
    const int krb = tid >> 4;
    const int qb  = (tid & 15) << 3;

    const float* pa = A + (size_t)(m0 + ra) * lda + ka;
    const float* pb = B + (size_t)krb * ldb + n0 + qb;

    float4 va0 = *reinterpret_cast<const float4*>(pa);
    float4 va1 = *reinterpret_cast<const float4*>(pa + 4);
    float4 vb0 = *reinterpret_cast<const float4*>(pb);
    float4 vb1 = *reinterpret_cast<const float4*>(pb + 4);

    #pragma unroll
    for (int ip = 0; ip < 4; ++ip)
        #pragma unroll
        for (int j = 0; j < 8; ++j) acc[ip][j] = 0ull;

    for (int k0 = 0; k0 < K; k0 += 16) {
        As[ka + 0][ra] = va0.x; As[ka + 1][ra] = va0.y;
        As[ka + 2][ra] = va0.z; As[ka + 3][ra] = va0.w;
        As[ka + 4][ra] = va1.x; As[ka + 5][ra] = va1.y;
        As[ka + 6][ra] = va1.z; As[ka + 7][ra] = va1.w;
        *reinterpret_cast<float4*>(&Bs[krb][qb])     = vb0;
        *reinterpret_cast<float4*>(&Bs[krb][qb + 4]) = vb1;
        __syncthreads();

        const int kn = k0 + 16;
        if (kn < K) {
            va0 = *reinterpret_cast<const float4*>(pa + kn);
            va1 = *reinterpret_cast<const float4*>(pa + kn + 4);
            vb0 = *reinterpret_cast<const float4*>(pb + (size_t)kn * ldb);
            vb1 = *reinterpret_cast<const float4*>(pb + (size_t)kn * ldb + 4);
        }

        #pragma unroll
        for (int kk = 0; kk < 16; ++kk) {
            const ulonglong2* ap =
                reinterpret_cast<const ulonglong2*>(&As[kk][ty << 3]);
            ulonglong2 aa = ap[0];
            ulonglong2 ab = ap[1];
            unsigned long long apair[4] = {aa.x, aa.y, ab.x, ab.y};
            float4 b0 = *reinterpret_cast<const float4*>(&Bs[kk][tx << 3]);
            float4 b1 = *reinterpret_cast<const float4*>(&Bs[kk][(tx << 3) + 4]);
            float bv[8] = {b0.x, b0.y, b0.z, b0.w, b1.x, b1.y, b1.z, b1.w};
            #pragma unroll
            for (int j = 0; j < 8; ++j) {
                unsigned long long bp;
                PACK2(bp, bv[j], bv[j]);
                #pragma unroll
                for (int ip = 0; ip < 4; ++ip)
                    FMA2(acc[ip][j], apair[ip], bp);
            }
        }
        __syncthreads();
    }
}

__device__ __forceinline__ void unpack_big(
    const unsigned long long acc[4][8], float r[8][8])
{
    #pragma unroll
    for (int ip = 0; ip < 4; ++ip)
        #pragma unroll
        for (int j = 0; j < 8; ++j)
            UNPACK2(r[2 * ip][j], r[2 * ip + 1][j], acc[ip][j]);
}

// ================= 128x64x16 core (8x4 micro), single-buffered ================
template<int EXP>
__device__ __forceinline__ void gemm_s_core(
    const float* __restrict__ A, int lda,
    const float* __restrict__ B, int ldb,
    int K, int m0, int n0, const float* __restrict__ sM,
    unsigned long long acc[4][4])
{
    __shared__ __align__(16) float As[16][132];
    __shared__ __align__(16) float Bs[16][68];

    const int tid = threadIdx.x;
    const int tx  = tid & 15;
    const int ty  = tid >> 4;

    const int ra  = tid >> 1;
    const int ka  = (tid & 1) << 3;
    const int krb = tid >> 4;
    const int qb  = (tid & 15) << 2;

    const float* pa = A + (size_t)(m0 + ra) * lda + ka;
    const float* pb = B + (size_t)krb * ldb + n0 + qb;
    const float Mr = EXP ? sM[ra] : 0.f;

    float4 va0 = *reinterpret_cast<const float4*>(pa);
    float4 va1 = *reinterpret_cast<const float4*>(pa + 4);
    float4 vb  = *reinterpret_cast<const float4*>(pb);

    #pragma unroll
    for (int ip = 0; ip < 4; ++ip)
        #pragma unroll
        for (int j = 0; j < 4; ++j) acc[ip][j] = 0ull;

    for (int k0 = 0; k0 < K; k0 += 16) {
        if (EXP) {
            As[ka + 0][ra] = __expf(va0.x - Mr);
            As[ka + 1][ra] = __expf(va0.y - Mr);
            As[ka + 2][ra] = __expf(va0.z - Mr);
            As[ka + 3][ra] = __expf(va0.w - Mr);
            As[ka + 4][ra] = __expf(va1.x - Mr);
            As[ka + 5][ra] = __expf(va1.y - Mr);
            As[ka + 6][ra] = __expf(va1.z - Mr);
            As[ka + 7][ra] = __expf(va1.w - Mr);
        } else {
            As[ka + 0][ra] = va0.x; As[ka + 1][ra] = va0.y;
            As[ka + 2][ra] = va0.z; As[ka + 3][ra] = va0.w;
            As[ka + 4][ra] = va1.x; As[ka + 5][ra] = va1.y;
            As[ka + 6][ra] = va1.z; As[ka + 7][ra] = va1.w;
        }
        *reinterpret_cast<float4*>(&Bs[krb][qb]) = vb;
        __syncthreads();

        const int kn = k0 + 16;
        if (kn < K) {
            va0 = *reinterpret_cast<const float4*>(pa + kn);
            va1 = *reinterpret_cast<const float4*>(pa + kn + 4);
            vb  = *reinterpret_cast<const float4*>(pb + (size_t)kn * ldb);
        }

        #pragma unroll
        for (int kk = 0; kk < 16; ++kk) {
            const ulonglong2* ap =
                reinterpret_cast<const ulonglong2*>(&As[kk][ty << 3]);
            ulonglong2 aa = ap[0];
            ulonglong2 ab = ap[1];
            unsigned long long apair[4] = {aa.x, aa.y, ab.x, ab.y};
            float4 b4 = *reinterpret_cast<const float4*>(&Bs[kk][tx << 2]);
            unsigned long long bp[4];
            PACK2(bp[0], b4.x, b4.x);
            PACK2(bp[1], b4.y, b4.y);
            PACK2(bp[2], b4.z, b4.z);
            PACK2(bp[3], b4.w, b4.w);
            #pragma unroll
            for (int ip = 0; ip < 4; ++ip)
                #pragma unroll
                for (int j = 0; j < 4; ++j)
                    FMA2(acc[ip][j], apair[ip], bp[j]);
        }
        __syncthreads();
    }
}

__device__ __forceinline__ void unpack_acc(
    const unsigned long long acc[4][4], float r[8][4])
{
    #pragma unroll
    for (int ip = 0; ip < 4; ++ip)
        #pragma unroll
        for (int j = 0; j < 4; ++j)
            UNPACK2(r[2 * ip][j], r[2 * ip + 1][j], acc[ip][j]);
}

// ---------------- 1) qkv = x @ w_qkv; scatter q, kT (transposed), v ------------
__global__ __launch_bounds__(256) void k_gemm_qkv(
    const float* __restrict__ x, const float* __restrict__ w)
{
    const int m0 = blockIdx.y * 128;
    const int n0 = blockIdx.x * 128;
    unsigned long long acc[4][8];
    gemm_big_core(x, HID, w, 3 * NHEAD * DH, HID, m0, n0, acc);
    float r[8][8];
    unpack_big(acc, r);

    const int tx = threadIdx.x & 15;
    const int ty = threadIdx.x >> 4;
    const int nb   = n0 + (tx << 3);
    const int sel  = nb / (NHEAD * DH);
    const int head = (nb % (NHEAD * DH)) >> 6;
    const int cih  = nb & 63;
    const int b    = m0 >> 10;
    const int tokb = (m0 & 1023) + (ty << 3);

    if (sel == 1) {
        #pragma unroll
        for (int j = 0; j < 8; ++j) {
            float* col = g_kT
                + ((size_t)(b * NHEAD + head) * DH + cih + j) * NTOK + tokb;
            *reinterpret_cast<float4*>(col) =
                make_float4(r[0][j], r[1][j], r[2][j], r[3][j]);
            *reinterpret_cast<float4*>(col + 4) =
                make_float4(r[4][j], r[5][j], r[6][j], r[7][j]);
        }
    } else {
        float* dst = (sel == 0) ? g_q : g_v;
        #pragma unroll
        for (int rr = 0; rr < 8; ++rr) {
            const int tok = tokb + rr;
            float* row = dst
                + (((size_t)(b * NHEAD + head) * NTOK + tok) << 6) + cih;
            *reinterpret_cast<float4*>(row) =
                make_float4(r[rr][0], r[rr][1], r[rr][2], r[rr][3]);
            *reinterpret_cast<float4*>(row + 4) =
                make_float4(r[rr][4], r[rr][5], r[rr][6], r[rr][7]);
        }
    }
}

// ---------------- 2) rel tables, smem-blocked: one block per (bh, qh) ----------
__global__ __launch_bounds__(256) void k_rel(
    const float* __restrict__ rel_pos_h, const float* __restrict__ rel_pos_w)
{
    __shared__ __align__(16) float qs[32][68];   // q rows for this token block
    __shared__ __align__(16) float rh[32][68];   // rel_pos_h rows qh+0 .. qh+31
    __shared__ __align__(16) float rw[63][68];   // all rel_pos_w rows

    const int qh = blockIdx.x;        // 0..31
    const int bh = blockIdx.y;        // 0..47
    const int tid = threadIdx.x;

    // loads (float4 granularity): qs/rh = 512 f4 each, rw = 1008 f4
    {
        const float* qsrc = g_q + (((size_t)bh << 10) + qh * 32) * DH;
        #pragma unroll
        for (int l = 0; l < 2; ++l) {
            int idx = tid + l * 256;              // 0..511
            int row = idx >> 4, c4 = (idx & 15) << 2;
            *reinterpret_cast<float4*>(&qs[row][c4]) =
                *reinterpret_cast<const float4*>(qsrc + (size_t)row * DH + c4);
            *reinterpret_cast<float4*>(&rh[row][c4]) =
                *reinterpret_cast<const float4*>(rel_pos_h + (size_t)(qh + row) * DH + c4);
        }
        #pragma unroll
        for (int l = 0; l < 4; ++l) {
            int idx = tid + l * 256;              // 0..1023
            if (idx < 1008) {
                int row = idx >> 4, c4 = (idx & 15) << 2;
                *reinterpret_cast<float4*>(&rw[row][c4]) =
                    *reinterpret_cast<const float4*>(rel_pos_w + (size_t)row * DH + c4);
            }
        }
    }
    __syncthreads();

    // outputs: rel_h (qw, kh) and rel_w (qw, kw); thread -> qw = tid>>3, 4 cols
    const int qw = tid >> 3;
    const int c0 = (tid & 7) << 2;                 // kh/kw base (4 outputs)
    const int tok = qh * 32 + qw;

    float oh[4] = {0.f, 0.f, 0.f, 0.f};
    float ow[4] = {0.f, 0.f, 0.f, 0.f};
    #pragma unroll
    for (int c = 0; c < 64; c += 4) {
        float4 qv = *reinterpret_cast<const float4*>(&qs[qw][c]);
        #pragma unroll
        for (int j = 0; j < 4; ++j) {
            const int kh = c0 + j;
            float4 hv = *reinterpret_cast<const float4*>(&rh[31 - kh][c]);
            oh[j] = fmaf(qv.x, hv.x, oh[j]);
            oh[j] = fmaf(qv.y, hv.y, oh[j]);
            oh[j] = fmaf(qv.z, hv.z, oh[j]);
            oh[j] = fmaf(qv.w, hv.w, oh[j]);
            const int kw = c0 + j;
            float4 wv = *reinterpret_cast<const float4*>(&rw[qw - kw + 31][c]);
            ow[j] = fmaf(qv.x, wv.x, ow[j]);
            ow[j] = fmaf(qv.y, wv.y, ow[j]);
            ow[j] = fmaf(qv.z, wv.z, ow[j]);
            ow[j] = fmaf(qv.w, wv.w, ow[j]);
        }
    }
    *reinterpret_cast<float4*>(
        &g_relh[(((size_t)bh << 10) + tok) * 32 + c0]) =
        make_float4(oh[0], oh[1], oh[2], oh[3]);
    *reinterpret_cast<float4*>(
        &g_relw[(((size_t)bh << 10) + tok) * 32 + c0]) =
        make_float4(ow[0], ow[1], ow[2], ow[3]);
}

// ---------------- 3) logits + bias + partial softmax stats ----------------
__global__ __launch_bounds__(256) void k_logits()
{
    const int bh = blockIdx.z;
    const int m0 = blockIdx.y * 128;
    const int n0 = blockIdx.x * 64;
    const float* A = g_q  + ((size_t)bh << 16);
    const float* B = g_kT + ((size_t)bh << 16);
    unsigned long long acc[4][4];
    gemm_s_core<0>(A, DH, B, NTOK, DH, m0, n0, nullptr, acc);
    float r[8][4];
    unpack_acc(acc, r);

    const int tx = threadIdx.x & 15;
    const int ty = threadIdx.x >> 4;
    const float scale = 0.125f;
    const int col0 = n0 + (tx << 2);
    const int kh   = col0 >> 5;
    const int kw0  = col0 & 31;
    const int ntile = blockIdx.x;
    float* outb = g_attn + ((size_t)bh << 20);

    #pragma unroll
    for (int rr = 0; rr < 8; ++rr) {
        const int tok = m0 + (ty << 3) + rr;
        const float* rh = g_relh + (((size_t)bh << 10) + tok) * 32;
        const float* rw = g_relw + (((size_t)bh << 10) + tok) * 32;
        const float bias = rh[kh];
        float4 v;
        v.x = fmaf(r[rr][0], scale, bias + rw[kw0 + 0]);
        v.y = fmaf(r[rr][1], scale, bias + rw[kw0 + 1]);
        v.z = fmaf(r[rr][2], scale, bias + rw[kw0 + 2]);
        v.w = fmaf(r[rr][3], scale, bias + rw[kw0 + 3]);
        *reinterpret_cast<float4*>(&outb[((size_t)tok << 10) + col0]) = v;

        float mx = fmaxf(fmaxf(v.x, v.y), fmaxf(v.z, v.w));
        #pragma unroll
        for (int o = 8; o > 0; o >>= 1)
            mx = fmaxf(mx, __shfl_xor_sync(0xffffffffu, mx, o));
        float s = __expf(v.x - mx) + __expf(v.y - mx)
                + __expf(v.z - mx) + __expf(v.w - mx);
        #pragma unroll
        for (int o = 8; o > 0; o >>= 1)
            s += __shfl_xor_sync(0xffffffffu, s, o);
        if (tx == 0) {
            const size_t pidx = ((size_t)bh << 14) + ((size_t)tok << 4) + ntile;
            g_pm[pidx] = mx;
            g_pl[pidx] = s;
        }
    }
}

// ---------------- 4) fused softmax + PV ----------------
__global__ __launch_bounds__(256) void k_pv()
{
    __shared__ float sM[128];
    __shared__ float sInvL[128];

    const int bh = blockIdx.y;
    const int m0 = blockIdx.x * 128;
    const int tid = threadIdx.x;

    if (tid < 128) {
        const int tok = m0 + tid;
        const float4* pm = (const float4*)(g_pm + ((size_t)bh << 14) + ((size_t)tok << 4));
        const float4* pl = (const float4*)(g_pl + ((size_t)bh << 14) + ((size_t)tok << 4));
        float4 m4[4] = {pm[0], pm[1], pm[2], pm[3]};
        float4 l4[4] = {pl[0], pl[1], pl[2], pl[3]};
        float M = -3.4e38f;
        #pragma unroll
        for (int i = 0; i < 4; ++i)
            M = fmaxf(M, fmaxf(fmaxf(m4[i].x, m4[i].y), fmaxf(m4[i].z, m4[i].w)));
        float L = 0.f;
        #pragma unroll
        for (int i = 0; i < 4; ++i) {
            L += l4[i].x * __expf(m4[i].x - M);
            L += l4[i].y * __expf(m4[i].y - M);
            L += l4[i].z * __expf(m4[i].z - M);
            L += l4[i].w * __expf(m4[i].w - M);
        }
        sM[tid] = M;
        sInvL[tid] = 1.0f / L;
    }
    __syncthreads();

    unsigned long long acc[4][4];
    gemm_s_core<1>(g_attn + ((size_t)bh << 20), NTOK,
                   g_v + ((size_t)bh << 16), DH,
                   NTOK, m0, 0, sM, acc);
    float r[8][4];
    unpack_acc(acc, r);

    const int tx = tid & 15;
    const int ty = tid >> 4;
    const int head = bh % NHEAD;
    const int b    = bh / NHEAD;

    #pragma unroll
    for (int rr = 0; rr < 8; ++rr) {
        const int rloc = (ty << 3) + rr;
        const int tok = m0 + rloc;
        const float inv = sInvL[rloc];
        float4 v4 = make_float4(r[rr][0] * inv, r[rr][1] * inv,
                                r[rr][2] * inv, r[rr][3] * inv);
        *reinterpret_cast<float4*>(
            &g_o[(size_t)(b * NTOK + tok) * HID + head * DH + (tx << 2)]) = v4;
    }
}

// ---------------- 5) final projection (big core) ----------------
__global__ __launch_bounds__(256) void k_out(
    const float* __restrict__ w, const float* __restrict__ bias,
    float* __restrict__ out)
{
    const int m0 = blockIdx.y * 128;
    const int n0 = blockIdx.x * 128;
    unsigned long long acc[4][8];
    gemm_big_core(g_o, HID, w, HID, HID, m0, n0, acc);
    float r[8][8];
    unpack_big(acc, r);

    const int tx = threadIdx.x & 15;
    const int ty = threadIdx.x >> 4;
    const int col0 = n0 + (tx << 3);
    float4 bb0 = *reinterpret_cast<const float4*>(&bias[col0]);
    float4 bb1 = *reinterpret_cast<const float4*>(&bias[col0 + 4]);

    #pragma unroll
    for (int rr = 0; rr < 8; ++rr) {
        const int m = m0 + (ty << 3) + rr;
        float* dst = &out[(size_t)m * HID + col0];
        *reinterpret_cast<float4*>(dst) =
            make_float4(r[rr][0] + bb0.x, r[rr][1] + bb0.y,
                        r[rr][2] + bb0.z, r[rr][3] + bb0.w);
        *reinterpret_cast<float4*>(dst + 4) =
            make_float4(r[rr][4] + bb1.x, r[rr][5] + bb1.y,
                        r[rr][6] + bb1.z, r[rr][7] + bb1.w);
    }
}

// ---------------- launcher ----------------
extern "C" void kernel_launch(void* const* d_in, const int* in_sizes, int n_in,
                              void* d_out, int out_size)
{
    const float* x         = (const float*)d_in[0];
    const float* w_qkv     = (const float*)d_in[1];
    const float* w_out     = (const float*)d_in[2];
    const float* b_out     = (const float*)d_in[3];
    const float* rel_pos_h = (const float*)d_in[4];
    const float* rel_pos_w = (const float*)d_in[5];
    float* out = (float*)d_out;

    k_gemm_qkv<<<dim3(18, 32), 256>>>(x, w_qkv);
    k_rel<<<dim3(32, BH), 256>>>(rel_pos_h, rel_pos_w);
    k_logits<<<dim3(16, 8, BH), 256>>>();
    k_pv<<<dim3(8, BH), 256>>>();
    k_out<<<dim3(6, 32), 256>>>(w_out, b_out, out);
}